// round 10
// baseline (speedup 1.0000x reference)
#include <cuda_runtime.h>

// MMD_53008486367839 — batched persistence-diagram MMD with RBF kernel.
// B=64, N=M=1024, WIDTH=DECAY=1.
//
// Mercer feature expansion (validated R7-R9):
//   mmd_b = sum_{a+b<=20} c_ab F_ab^2,  c_ab = 2^(a+b)/(a! b!),
//   F_ab  = sum_i s_i e^{-u_i^2-v_i^2} u_i^a v_i^b,  s_i = +lt (X), -lt (Y).
//
// R10: register-resident power chains. One warp per column-pair (b, 20-b):
//   F_{a,b} = sum_i (ps_i v_i^b) u_i^a  — serial u-chain per point with one
// accumulate per a, all in registers (templated on b -> full unroll). Lanes
// stream point PAIRS with packed f32x2 math (2 points per FMA-pipe instr).
// Shared traffic drops from 462 words/point to 3 words/point.
// Single launch; last-block (counter) reduce writes out[0].

#define BATCH 64
#define NPTS  1024
#define D     20
#define NCOL  21            // columns b = 0..20
#define NSLOT 441           // NCOL*NCOL storage slots (col*21 + a)
#define NSLOTP 448
#define CPB   2             // chunks per batch (chunk0 = X, chunk1 = Y)
#define GRID  (BATCH * CPB) // 128
#define TPB   352           // 11 warps = 11 column-pair slots
#define NITER 16            // 1024 points / (32 lanes * 2 packed)

__device__ float g_F[BATCH][CPB][NSLOTP];
__device__ int   g_ctr;     // zero-init; reset by last block each call

__constant__ float c_inv_fact[NCOL] = {
    1.0f, 1.0f, 0.5f, 1.6666666666666666e-01f, 4.1666666666666664e-02f,
    8.3333333333333332e-03f, 1.3888888888888889e-03f, 1.9841269841269841e-04f,
    2.4801587301587302e-05f, 2.7557319223985893e-06f, 2.7557319223985888e-07f,
    2.5052108385441720e-08f, 2.0876756987868100e-09f, 1.6059043836821613e-10f,
    1.1470745597729725e-11f, 7.6471637318198164e-13f, 4.7794773323873853e-14f,
    2.8114572543455206e-15f, 1.5619206968586226e-16f, 8.2206352466243295e-18f,
    4.1103176233121648e-19f};

typedef unsigned long long ull;

__device__ __forceinline__ ull add2(ull a, ull b) {
    ull r; asm("add.rn.f32x2 %0, %1, %2;" : "=l"(r) : "l"(a), "l"(b)); return r;
}
__device__ __forceinline__ ull mul2(ull a, ull b) {
    ull r; asm("mul.rn.f32x2 %0, %1, %2;" : "=l"(r) : "l"(a), "l"(b)); return r;
}
__device__ __forceinline__ float lo2(ull a) { return __uint_as_float((unsigned)a); }
__device__ __forceinline__ float hi2(ull a) { return __uint_as_float((unsigned)(a >> 32)); }
__device__ __forceinline__ ull lds64(unsigned addr) {
    ull r; asm volatile("ld.shared.b64 %0, [%1];" : "=l"(r) : "r"(addr)); return r;
}
__device__ __forceinline__ float ex2f_(float x) {
    float y; asm("ex2.approx.ftz.f32 %0, %1;" : "=f"(y) : "f"(x)); return y;
}
__device__ __forceinline__ float wredsum(float s) {
    #pragma unroll
    for (int o = 16; o > 0; o >>= 1) s += __shfl_down_sync(0xFFFFFFFFu, s, o);
    return s;
}

// Warp worker for column pair (B1, 20-B1). B1==10 handles only column 10.
template<int B1>
__device__ __forceinline__ void chain_run(unsigned au, unsigned av, unsigned ap,
                                          int lane, float* __restrict__ gdst) {
    constexpr int B2 = D - B1;
    constexpr int NA = NCOL - B1;              // col B1: a = 0..20-B1
    constexpr int NB = (B1 == 10) ? 0 : (B1 + 1);  // col B2: a = 0..B1

    ull accA[NA];
    ull accB[NB > 0 ? NB : 1];
    #pragma unroll
    for (int a = 0; a < NA; a++) accA[a] = 0ull;
    #pragma unroll
    for (int a = 0; a < (NB > 0 ? NB : 1); a++) accB[a] = 0ull;

    #pragma unroll 2
    for (int j = 0; j < NITER; j++) {
        unsigned off = (unsigned)((j * 32 + lane) * 8);   // point pair (2i, 2i+1)
        ull u2 = lds64(au + off);
        ull v2 = lds64(av + off);
        ull pv = lds64(ap + off);                         // ps

        #pragma unroll
        for (int k = 0; k < B1; k++) pv = mul2(pv, v2);   // ps * v^B1
        ull pvA = pv;
        #pragma unroll
        for (int k = B1; k < B2; k++) pv = mul2(pv, v2);  // ps * v^B2

        ull pw = pvA;                                     // column B1 u-chain
        #pragma unroll
        for (int a = 0; a < NA; a++) {
            accA[a] = add2(accA[a], pw);
            if (a + 1 < NA) pw = mul2(pw, u2);
        }
        if (NB > 0) {                                     // column B2 u-chain
            pw = pv;
            #pragma unroll
            for (int a = 0; a < NB; a++) {
                accB[a] = add2(accB[a], pw);
                if (a + 1 < NB) pw = mul2(pw, u2);
            }
        }
    }

    // lane-reduce each accumulator; lane 0 stores
    #pragma unroll
    for (int a = 0; a < NA; a++) {
        float s = wredsum(lo2(accA[a]) + hi2(accA[a]));
        if (lane == 0) gdst[B1 * NCOL + a] = s;
    }
    #pragma unroll
    for (int a = 0; a < NB; a++) {
        float s = wredsum(lo2(accB[a]) + hi2(accB[a]));
        if (lane == 0) gdst[B2 * NCOL + a] = s;
    }
}

__global__ void __launch_bounds__(TPB) mmd_fused(const float* __restrict__ X,
                                                 const float* __restrict__ Y,
                                                 const float* __restrict__ weights,
                                                 const float* __restrict__ num_samples,
                                                 float* __restrict__ out) {
    __shared__ __align__(8) float su[NPTS];
    __shared__ __align__(8) float sv[NPTS];
    __shared__ __align__(8) float sps[NPTS];
    __shared__ int   s_rank;
    __shared__ float sws[BATCH];
    __shared__ float warp_sums[11];

    const int blk   = blockIdx.x;
    const int b     = blk >> 1;
    const int chunk = blk & 1;
    const int t     = threadIdx.x;

    // ---- stage: transform this chunk's 1024 points into shared ----
    {
        const float* src  = chunk ? Y : X;
        const float  sign = chunk ? -1.0f : 1.0f;
        const float  LOG2E = 1.4426950408889634f;
        #pragma unroll 1
        for (int i = t; i < NPTS; i += TPB) {
            float2 xy = __ldg((const float2*)(src + ((size_t)b * NPTS + i) * 2));
            float u = xy.x, v = xy.y - xy.x;       // (birth, lifetime)
            su[i]  = u;
            sv[i]  = v;
            sps[i] = sign * v * ex2f_(-fmaf(u, u, v * v) * LOG2E);
        }
    }
    __syncthreads();

    const int wid = t >> 5, lane = t & 31;
    unsigned au = (unsigned)__cvta_generic_to_shared(su);
    unsigned av = (unsigned)__cvta_generic_to_shared(sv);
    unsigned ap = (unsigned)__cvta_generic_to_shared(sps);
    float* gdst = &g_F[b][chunk][0];

    switch (wid) {
        case 0:  chain_run<0 >(au, av, ap, lane, gdst); break;
        case 1:  chain_run<1 >(au, av, ap, lane, gdst); break;
        case 2:  chain_run<2 >(au, av, ap, lane, gdst); break;
        case 3:  chain_run<3 >(au, av, ap, lane, gdst); break;
        case 4:  chain_run<4 >(au, av, ap, lane, gdst); break;
        case 5:  chain_run<5 >(au, av, ap, lane, gdst); break;
        case 6:  chain_run<6 >(au, av, ap, lane, gdst); break;
        case 7:  chain_run<7 >(au, av, ap, lane, gdst); break;
        case 8:  chain_run<8 >(au, av, ap, lane, gdst); break;
        case 9:  chain_run<9 >(au, av, ap, lane, gdst); break;
        default: chain_run<10>(au, av, ap, lane, gdst); break;
    }

    // ---- completion count ----
    __threadfence();
    __syncthreads();
    if (t == 0) s_rank = atomicAdd(&g_ctr, 1);
    __syncthreads();
    if (s_rank != GRID - 1) return;

    // ================= last block: reduce =================
    __threadfence();

    if (t < BATCH) {
        float n = __ldg(&num_samples[t]);
        sws[t] = __ldg(&weights[t]) / (n * n);
    }
    __syncthreads();

    float val = 0.f;
    #pragma unroll 1
    for (int idx = t; idx < BATCH * NSLOT; idx += TPB) {
        int b2  = idx / NSLOT;
        int k   = idx - b2 * NSLOT;
        int col = k / NCOL;
        int a   = k - col * NCOL;
        if (a + col <= D) {
            float F = g_F[b2][0][k] + g_F[b2][1][k];
            float c = exp2f((float)(a + col)) * c_inv_fact[a] * c_inv_fact[col];
            val = fmaf(sws[b2] * c * F, F, val);
        }
    }

    val = wredsum(val);
    if (lane == 0) warp_sums[wid] = val;
    __syncthreads();

    if (t == 0) {
        float bs = 0.f;
        #pragma unroll
        for (int w = 0; w < 11; w++) bs += warp_sums[w];
        out[0] = bs;
        g_ctr  = 0;                       // reset for next replay
    }
}

// ---------------------------------------------------------------------------
extern "C" void kernel_launch(void* const* d_in, const int* in_sizes, int n_in,
                              void* d_out, int out_size) {
    const float* X  = (const float*)d_in[0];
    const float* Y  = (const float*)d_in[1];
    const float* w  = (const float*)d_in[2];
    const float* ns = (const float*)d_in[3];
    float* out = (float*)d_out;

    mmd_fused<<<GRID, TPB>>>(X, Y, w, ns, out);
}

// round 13
// speedup vs baseline: 2.4105x; 2.4105x over previous
#include <cuda_runtime.h>

// MMD_53008486367839 — batched persistence-diagram MMD with RBF kernel.
// B=64, N=M=1024, WIDTH=DECAY=1.
//
// Mercer feature expansion (validated R7-R10):
//   mmd_b = sum_{a+b<=20} c_ab F_ab^2,  c_ab = 2^(a+b)/(a! b!),
//   F_ab  = sum_i ps_i u_i^a v_i^b,  ps_i = s_i e^{-u^2-v^2},
//   s_i = +lifetime (X), -lifetime (Y).
//
// R12 = R11 with shared-bounds fix: F as a tiny GEMM
//   F[a][b] = sum_i (ps u^a)[i] * (v^b)[i].
//  - block = one 256-point tile (8 blocks per batch, grid 512, one wave)
//  - phase 1: power rows padded to 24: spu[24][257], spv[24][257] (48.2 KB,
//    stride 257 -> row-major reads conflict-free); rows 21..23 exist only so
//    edge 4x4 tiles read in-bounds (their products are masked in the reduce)
//  - phase 2: warp = 32-point K-chunk; lane = 4x4 (a,b) register tile
//    (21 active tiles of {ta+tb<=5}), 8 LDS feed 16 FMAs
//  - per-batch counter: 8th block of each batch reduces that batch's
//    partials; a final counter thread sums 64 batch values in fixed order.
// Single launch, zero-free, deterministic.

#define BATCH 64
#define NPTS  1024
#define D     20
#define NROW  24             // padded power rows (a,b = 0..23; 21..23 masked)
#define STR   257            // shared row stride (words); 257 % 32 == 1
#define CPB   8              // chunks (blocks) per batch
#define TILEPTS 256
#define GRID  (BATCH * CPB)  // 512
#define NSL   512            // 32 lanes * 16 slots per block

__device__ float g_part[GRID][NSL];   // per-block feature partials
__device__ float g_bval[BATCH];       // per-batch weighted results
__device__ int   g_bctr[BATCH];       // zero-init; reset after use
__device__ int   g_fctr;

__constant__ float c_inv_fact[NROW] = {
    1.0f, 1.0f, 0.5f, 1.6666666666666666e-01f, 4.1666666666666664e-02f,
    8.3333333333333332e-03f, 1.3888888888888889e-03f, 1.9841269841269841e-04f,
    2.4801587301587302e-05f, 2.7557319223985893e-06f, 2.7557319223985888e-07f,
    2.5052108385441720e-08f, 2.0876756987868100e-09f, 1.6059043836821613e-10f,
    1.1470745597729725e-11f, 7.6471637318198164e-13f, 4.7794773323873853e-14f,
    2.8114572543455206e-15f, 1.5619206968586226e-16f, 8.2206352466243295e-18f,
    4.1103176233121648e-19f, 0.0f, 0.0f, 0.0f};   // 21..23 masked

// lane -> 4x4 tile origin (ta,tb), enumeration of {ta+tb<=5} (21 tiles);
// lanes 21..31 duplicate tile 0 (results masked out in the reduce).
__constant__ unsigned char c_ta[32] =
    {0,0,0,0,0,0, 1,1,1,1,1, 2,2,2,2, 3,3,3, 4,4, 5, 0,0,0,0,0,0,0,0,0,0,0};
__constant__ unsigned char c_tb[32] =
    {0,1,2,3,4,5, 0,1,2,3,4, 0,1,2,3, 0,1,2, 0,1, 0, 0,0,0,0,0,0,0,0,0,0,0};

__device__ __forceinline__ float ex2f_(float x) {
    float y; asm("ex2.approx.ftz.f32 %0, %1;" : "=f"(y) : "f"(x)); return y;
}

__global__ void __launch_bounds__(256) mmd_fused(const float* __restrict__ X,
                                                 const float* __restrict__ Y,
                                                 const float* __restrict__ weights,
                                                 const float* __restrict__ num_samples,
                                                 float* __restrict__ out) {
    __shared__ __align__(16) float smem[2 * NROW * STR];  // spu | spv, 48.2 KB
    __shared__ float warp_sums[8];
    __shared__ int   s_rank;

    const int blk   = blockIdx.x;
    const int b     = blk >> 3;
    const int chunk = blk & 7;
    const int t     = threadIdx.x;
    const int lane  = t & 31, wid = t >> 5;

    // ---- phase 1: one point per thread -> power rows in shared ----
    {
        int p = chunk * TILEPTS + t;          // merged index 0..2047
        float2 xy; float sgn;
        if (p < NPTS) {
            xy = __ldg((const float2*)(X + ((size_t)b * NPTS + p) * 2));
            sgn = 1.0f;
        } else {
            xy = __ldg((const float2*)(Y + ((size_t)b * NPTS + (p - NPTS)) * 2));
            sgn = -1.0f;
        }
        const float LOG2E = 1.4426950408889634f;
        float u = xy.x, v = xy.y - xy.x;      // (birth, lifetime)
        float ps = sgn * v * ex2f_(-fmaf(u, u, v * v) * LOG2E);

        float pw = ps;
        smem[t] = pw;                         // spu row 0 = ps
        #pragma unroll
        for (int a = 1; a < NROW; a++) { pw *= u; smem[a * STR + t] = pw; }
        pw = 1.0f;
        smem[NROW * STR + t] = 1.0f;          // spv row 0 = 1
        #pragma unroll
        for (int bb = 1; bb < NROW; bb++) { pw *= v; smem[(NROW + bb) * STR + t] = pw; }
    }
    __syncthreads();

    // ---- phase 2: 4x4 register tile per lane, 32-point K-chunk per warp ----
    float acc[16];
    #pragma unroll
    for (int r = 0; r < 16; r++) acc[r] = 0.0f;
    {
        const float* pu = smem + 4 * (int)c_ta[lane] * STR;            // rows <= 23
        const float* pv = smem + (NROW + 4 * (int)c_tb[lane]) * STR;   // rows <= 23
        const int base = wid * 32;
        #pragma unroll 4
        for (int j = 0; j < 32; j++) {
            int i = base + j;
            float a0 = pu[i], a1 = pu[STR + i], a2 = pu[2 * STR + i], a3 = pu[3 * STR + i];
            float b0 = pv[i], b1 = pv[STR + i], b2 = pv[2 * STR + i], b3 = pv[3 * STR + i];
            acc[ 0] = fmaf(a0, b0, acc[ 0]);
            acc[ 1] = fmaf(a0, b1, acc[ 1]);
            acc[ 2] = fmaf(a0, b2, acc[ 2]);
            acc[ 3] = fmaf(a0, b3, acc[ 3]);
            acc[ 4] = fmaf(a1, b0, acc[ 4]);
            acc[ 5] = fmaf(a1, b1, acc[ 5]);
            acc[ 6] = fmaf(a1, b2, acc[ 6]);
            acc[ 7] = fmaf(a1, b3, acc[ 7]);
            acc[ 8] = fmaf(a2, b0, acc[ 8]);
            acc[ 9] = fmaf(a2, b1, acc[ 9]);
            acc[10] = fmaf(a2, b2, acc[10]);
            acc[11] = fmaf(a2, b3, acc[11]);
            acc[12] = fmaf(a3, b0, acc[12]);
            acc[13] = fmaf(a3, b1, acc[13]);
            acc[14] = fmaf(a3, b2, acc[14]);
            acc[15] = fmaf(a3, b3, acc[15]);
        }
    }
    __syncthreads();   // done reading power rows; smem now reusable

    // ---- cross-warp reduce via aliased shared [8][512], store partials ----
    {
        float* sacc = smem;
        #pragma unroll
        for (int r = 0; r < 16; r++)
            sacc[wid * NSL + lane * 16 + r] = acc[r];
        __syncthreads();
        float* gp = g_part[blk];
        #pragma unroll
        for (int s = t; s < NSL; s += 256) {
            float v2 = 0.0f;
            #pragma unroll
            for (int w = 0; w < 8; w++) v2 += sacc[w * NSL + s];
            gp[s] = v2;
        }
    }

    // ---- per-batch completion counter ----
    __threadfence();
    __syncthreads();
    if (t == 0) s_rank = atomicAdd(&g_bctr[b], 1);
    __syncthreads();
    if (s_rank != CPB - 1) return;

    // ======== batch reduce (last block of this batch; 64 run in parallel) ===
    if (t == 0) g_bctr[b] = 0;               // reset for next replay
    __threadfence();

    float val = 0.0f;
    #pragma unroll
    for (int s = t; s < NSL; s += 256) {
        int ln = s >> 4, r = s & 15;
        int A  = 4 * (int)c_ta[ln] + (r >> 2);     // <= 23, in-bounds of tables
        int Bc = 4 * (int)c_tb[ln] + (r & 3);
        float F = 0.0f;
        #pragma unroll
        for (int c2 = 0; c2 < CPB; c2++) F += g_part[(b << 3) | c2][s];
        bool valid = (ln < 21) && (A + Bc <= D);
        float coeff = valid ? exp2f((float)(A + Bc)) * c_inv_fact[A] * c_inv_fact[Bc]
                            : 0.0f;
        val = fmaf(coeff * F, F, val);
    }

    #pragma unroll
    for (int o = 16; o > 0; o >>= 1)
        val += __shfl_down_sync(0xFFFFFFFFu, val, o);
    if (lane == 0) warp_sums[wid] = val;
    __syncthreads();

    if (t == 0) {
        float bs = 0.0f;
        #pragma unroll
        for (int w = 0; w < 8; w++) bs += warp_sums[w];
        float n = __ldg(&num_samples[b]);
        g_bval[b] = bs * __ldg(&weights[b]) / (n * n);

        __threadfence();
        int rank = atomicAdd(&g_fctr, 1);
        if (rank == BATCH - 1) {
            __threadfence();
            float tot = 0.0f;
            #pragma unroll 8
            for (int i = 0; i < BATCH; i++) tot += g_bval[i];
            out[0] = tot;
            g_fctr = 0;                       // reset for next replay
        }
    }
}

// ---------------------------------------------------------------------------
extern "C" void kernel_launch(void* const* d_in, const int* in_sizes, int n_in,
                              void* d_out, int out_size) {
    const float* X  = (const float*)d_in[0];
    const float* Y  = (const float*)d_in[1];
    const float* w  = (const float*)d_in[2];
    const float* ns = (const float*)d_in[3];
    float* out = (float*)d_out;

    mmd_fused<<<GRID, 256>>>(X, Y, w, ns, out);
}